// round 5
// baseline (speedup 1.0000x reference)
#include <cuda_runtime.h>
#include <math.h>

#define BN 64
#define SN 512
#define DN 768
#define HN 384
#define GN 1536
#define TN 22

#define NBLK_REC 128
#define REC_THREADS 256

// ---------------- scratch (static device globals; zero-initialized) ---------
__device__ float g_embeds[BN * SN * DN];
__device__ float g_xg[2 * SN * BN * GN];                 // [dir][t][b][4H]
__device__ float g_lstm[BN * SN * 2 * HN];               // [b][t][2H]
__device__ float g_h[2 * 2 * BN * HN];                   // [dir][parity][b][H]
__device__ int   g_n[BN];
__device__ int   g_sent[BN];
__device__ int   g_last[BN];
__device__ volatile unsigned g_bar_gen2[2];
__device__ unsigned g_bar_cnt2[2];

// ---------------- packed fp32x2 helpers --------------------------------------
__device__ __forceinline__ unsigned long long fma2(unsigned long long a,
                                                   unsigned long long b,
                                                   unsigned long long c) {
    unsigned long long d;
    asm("fma.rn.f32x2 %0, %1, %2, %3;" : "=l"(d) : "l"(a), "l"(b), "l"(c));
    return d;
}
__device__ __forceinline__ float unpack_sum(unsigned long long v) {
    float lo, hi;
    asm("mov.b64 {%0, %1}, %2;" : "=f"(lo), "=f"(hi) : "l"(v));
    return lo + hi;
}
__device__ __forceinline__ float tanh_fast(float x) {
    float y;
    asm("tanh.approx.f32 %0, %1;" : "=f"(y) : "f"(x));
    return y;
}
__device__ __forceinline__ float sig_fast(float x) {
    return 0.5f * tanh_fast(0.5f * x) + 0.5f;
}

// ---------------- index helpers ----------------------------------------------
__device__ __forceinline__ long long ld_idx(const void* p, int i, bool is64) {
    return is64 ? ((const long long*)p)[i] : (long long)((const int*)p)[i];
}
__device__ __forceinline__ bool detect_is64(const void* start_ids) {
    return ((const int*)start_ids)[1] == 0;
}

// ---------------- K0: per-batch metadata --------------------------------------
__global__ void meta_kernel(const void* start_ids, const void* masks) {
    int b = blockIdx.x;
    int tid = threadIdx.x;
    bool is64 = detect_is64(start_ids);
    __shared__ int red[256];
    int cnt = 0, sm = 0;
    for (int t = tid; t < SN; t += 256) {
        long long sv = ld_idx(start_ids, b * SN + t, is64);
        long long mv = ld_idx(masks, b * SN + t, is64);
        cnt += (sv >= 0);
        sm += (int)mv;
    }
    red[tid] = cnt; __syncthreads();
    for (int o = 128; o > 0; o >>= 1) { if (tid < o) red[tid] += red[tid + o]; __syncthreads(); }
    int ntot = red[0]; __syncthreads();
    red[tid] = sm; __syncthreads();
    for (int o = 128; o > 0; o >>= 1) { if (tid < o) red[tid] += red[tid + o]; __syncthreads(); }
    int stot = red[0];
    if (tid == 0) {
        g_n[b] = ntot;
        g_sent[b] = stot;
        long long last = 0;
        if (ntot > 0) last = ld_idx(start_ids, b * SN + ntot - 1, is64);
        g_last[b] = (int)last;
    }
}

// ---------------- K1: align gather ---------------------------------------------
__global__ void gather_kernel(const float* __restrict__ hs, const void* __restrict__ start_ids) {
    int t = blockIdx.x, b = blockIdx.y;
    int sent = g_sent[b];
    if (t >= sent) return;
    bool is64 = detect_is64(start_ids);
    int n = g_n[b];
    long long idx;
    if (t == 0)      idx = 0;
    else if (t < n)  idx = ld_idx(start_ids, b * SN + t, is64) - 1;
    else if (t == n) idx = g_last[b];
    else             idx = 0;
    if (idx < 0) idx = 0;
    if (idx > SN - 1) idx = SN - 1;
    const float4* src = (const float4*)(hs + ((size_t)b * SN + (size_t)idx) * DN);
    float4* dst = (float4*)(g_embeds + ((size_t)b * SN + t) * DN);
    dst[threadIdx.x] = src[threadIdx.x];
}

// ---------------- K2: input projection GEMM (f32x2, cp.async, 2 blocks/SM) -----
// tile 128 (t) x 64 (n), micro 8x4, Bs XOR-swizzled to kill dRow=8 bank conflict
__global__ void __launch_bounds__(256, 2) proj_kernel(
    const float* __restrict__ Wf, const float* __restrict__ Wb,
    const float* __restrict__ bihf, const float* __restrict__ bhhf,
    const float* __restrict__ bihb, const float* __restrict__ bhhb)
{
    int b = blockIdx.z & 63;
    int dir = blockIdx.z >> 6;
    int sent = g_sent[b];
    int t0 = blockIdx.y * 128;
    if (t0 >= sent) return;
    int n0 = blockIdx.x * 64;

    const float* W   = dir ? Wb   : Wf;
    const float* bih = dir ? bihb : bihf;
    const float* bhh = dir ? bhhb : bhhf;

    __shared__ float As[2][128][20];
    __shared__ float Bs[2][64][20];

    int tid = threadIdx.x;
    int tx = tid & 15, ty = tid >> 4;
    int bsw = ((tx >> 3) & 1) << 2;   // Bs read swizzle (uniform in j)

    unsigned long long acc[8][4];
    #pragma unroll
    for (int i = 0; i < 8; i++)
        #pragma unroll
        for (int j = 0; j < 4; j++) acc[i][j] = 0ull;

    #define PROJ_FILL(stg, kt)                                                           \
        do {                                                                             \
            _Pragma("unroll")                                                            \
            for (int f = 0; f < 2; f++) {                                                \
                int lin = tid + f * 256;                                                 \
                int row = lin >> 2;                                                      \
                int c = (lin & 3) * 4;                                                   \
                unsigned sa = (unsigned)__cvta_generic_to_shared(&As[stg][row][c]);      \
                const float* ga = &g_embeds[((size_t)b * SN + t0 + row) * DN + (kt) + c];\
                asm volatile("cp.async.ca.shared.global [%0], [%1], 16;" :: "r"(sa), "l"(ga)); \
            }                                                                            \
            {                                                                            \
                int row = tid >> 2;                                                      \
                int c = (tid & 3) * 4;                                                   \
                int cs = c ^ (((row >> 3) & 1) << 2);                                    \
                unsigned sb = (unsigned)__cvta_generic_to_shared(&Bs[stg][row][cs]);     \
                const float* gb = &W[(size_t)(n0 + row) * DN + (kt) + c];                \
                asm volatile("cp.async.ca.shared.global [%0], [%1], 16;" :: "r"(sb), "l"(gb)); \
            }                                                                            \
            asm volatile("cp.async.commit_group;");                                      \
        } while (0)

    PROJ_FILL(0, 0);
    int st = 0;
    for (int kt = 0; kt < DN; kt += 16) {
        if (kt + 16 < DN) {
            PROJ_FILL(st ^ 1, kt + 16);
            asm volatile("cp.async.wait_group 1;");
        } else {
            asm volatile("cp.async.wait_group 0;");
        }
        __syncthreads();

        #pragma unroll
        for (int k = 0; k < 16; k += 4) {
            unsigned long long b0[4], b1[4];
            #pragma unroll
            for (int j = 0; j < 4; j++) {
                ulonglong2 v = *(const ulonglong2*)&Bs[st][tx + j * 16][k ^ bsw];
                b0[j] = v.x; b1[j] = v.y;
            }
            #pragma unroll
            for (int i = 0; i < 8; i++) {
                ulonglong2 av = *(const ulonglong2*)&As[st][ty + i * 16][k];
                #pragma unroll
                for (int j = 0; j < 4; j++) {
                    acc[i][j] = fma2(av.x, b0[j], acc[i][j]);
                    acc[i][j] = fma2(av.y, b1[j], acc[i][j]);
                }
            }
        }
        __syncthreads();
        st ^= 1;
    }
    #undef PROJ_FILL

    float bsj[4];
    #pragma unroll
    for (int j = 0; j < 4; j++) {
        int n = n0 + tx + j * 16;
        bsj[j] = bih[n] + bhh[n];
    }
    #pragma unroll
    for (int i = 0; i < 8; i++) {
        int t = t0 + ty + i * 16;
        if (t < sent) {
            float* dst = &g_xg[((size_t)(dir * SN + t) * BN + b) * GN + n0 + tx];
            #pragma unroll
            for (int j = 0; j < 4; j++)
                dst[j * 16] = unpack_sum(acc[i][j]) + bsj[j];
        }
    }
}

// ---------------- K3: persistent bidirectional LSTM recurrence -----------------
// 128 blocks (64/dir). Per block: 24 gate-rows (6 hidden units x 4 gates).
// 256 threads = 8 warps; warp = k-group (48 k each); lane = batch (nb=2: l, l+32).
__global__ void __launch_bounds__(REC_THREADS) lstm_kernel(
    const float* __restrict__ Whhf, const float* __restrict__ Whhb,
    const float* __restrict__ bihf, const float* __restrict__ bhhf,
    const float* __restrict__ bihb, const float* __restrict__ bhhb,
    const float* __restrict__ h0, const float* __restrict__ c0)
{
    extern __shared__ float sm_[];
    float* ws     = sm_;                         // 24*384 = 9216
    float* hs     = sm_ + 9216;                  // 8*64*52 = 26624
    float* P      = sm_ + 9216 + 26624;          // 8*24*65 = 12480
    float* bias_s = P + 12480;                   // 24
    int*   sent_s = (int*)(bias_s + 24);         // 64

    int tid = threadIdx.x;
    int blk = blockIdx.x;
    int dir = blk >> 6;
    int j0 = (blk & 63) * 6;

    const float* Whh = dir ? Whhb : Whhf;
    const float* bih = dir ? bihb : bihf;
    const float* bhh = dir ? bhhb : bhhf;

    for (int idx = tid; idx < 24 * HN; idx += REC_THREADS) {
        int r = idx / HN, k = idx % HN;
        int wrow = (r / 6) * HN + j0 + (r % 6);
        ws[r * HN + k] = Whh[(size_t)wrow * HN + k];
    }
    if (tid < 24) {
        int ng = (tid / 6) * HN + j0 + (tid % 6);
        bias_s[tid] = bih[ng] + bhh[ng];
    }
    if (tid < BN) sent_s[tid] = g_sent[tid];

    // cell ownership: pair pp -> idx = tid + pp*256 (valid if < 384)
    int be0 = tid / 6, je0 = tid % 6;
    int idx1 = tid + 256;
    int be1 = idx1 / 6, je1 = idx1 % 6;
    bool p1v = (idx1 < 384);

    g_h[((dir * 2 + 0) * BN + be0) * HN + j0 + je0] = h0[((size_t)dir * BN + be0) * HN + j0 + je0];
    float c0r = c0[((size_t)dir * BN + be0) * HN + j0 + je0];
    float c1r = 0.f;
    if (p1v) {
        g_h[((dir * 2 + 0) * BN + be1) * HN + j0 + je1] = h0[((size_t)dir * BN + be1) * HN + j0 + je1];
        c1r = c0[((size_t)dir * BN + be1) * HN + j0 + je1];
    }

    int kg = tid >> 5;               // warp = k-group
    int lane = tid & 31;
    int kbase = kg * 48;
    const float* hb0 = &hs[(kg * 64 + lane) * 52];
    const float* hb1 = &hs[(kg * 64 + lane + 32) * 52];
    const float* wkb = &ws[kbase];

    unsigned my_gen = 0;

    // ---- initial per-dir barrier (h0 published) ----
    __syncthreads();
    if (tid == 0) {
        __threadfence();
        unsigned tk = atomicAdd(&g_bar_cnt2[dir], 1u);
        if (tk == 63) { g_bar_cnt2[dir] = 0; __threadfence(); g_bar_gen2[dir] = my_gen + 1; }
        while (g_bar_gen2[dir] <= my_gen) { __nanosleep(32); }
        __threadfence();
    }
    __syncthreads();
    my_gen++;

    for (int s = 0; s < SN; s++) {
        int p = s & 1;
        int t = dir ? (SN - 1 - s) : s;

        // prefetch xg for cell (consumed after GEMV)
        const float* xb0 = &g_xg[((size_t)(dir * SN + t) * BN + be0) * GN + j0 + je0];
        const float* xb1 = &g_xg[((size_t)(dir * SN + t) * BN + be1) * GN + j0 + je1];
        float xp0[4], xp1[4];
        #pragma unroll
        for (int g = 0; g < 4; g++) xp0[g] = xb0[g * HN];
        if (p1v) {
            #pragma unroll
            for (int g = 0; g < 4; g++) xp1[g] = xb1[g * HN];
        }

        // stage this warp's h slice via cp.async (two halves)
        const float* hsrc = g_h + (size_t)(dir * 2 + p) * BN * HN;
        #pragma unroll
        for (int half = 0; half < 2; half++) {
            #pragma unroll
            for (int rr = 0; rr < 2; rr++) {
                int b2 = lane + rr * 32;
                #pragma unroll
                for (int c = 0; c < 6; c++) {
                    int kk = half * 24 + c * 4;
                    unsigned sd = (unsigned)__cvta_generic_to_shared(&hs[(kg * 64 + b2) * 52 + kk]);
                    const float* gsrc = hsrc + (size_t)b2 * HN + kbase + kk;
                    asm volatile("cp.async.ca.shared.global [%0], [%1], 16;" :: "r"(sd), "l"(gsrc));
                }
            }
            asm volatile("cp.async.commit_group;");
        }

        // GEMV: 24 rows x 2 batches, k-slice 48, packed f32x2
        unsigned long long a0[24], a1[24];
        #pragma unroll
        for (int r = 0; r < 24; r++) { a0[r] = 0ull; a1[r] = 0ull; }

        asm volatile("cp.async.wait_group 1;");
        #pragma unroll 2
        for (int ch = 0; ch < 6; ch++) {
            int kk = ch * 4;
            ulonglong2 h0v = *(const ulonglong2*)(hb0 + kk);
            ulonglong2 h1v = *(const ulonglong2*)(hb1 + kk);
            #pragma unroll
            for (int r = 0; r < 24; r++) {
                ulonglong2 wv = *(const ulonglong2*)(wkb + r * HN + kk);
                a0[r] = fma2(h0v.x, wv.x, a0[r]);
                a0[r] = fma2(h0v.y, wv.y, a0[r]);
                a1[r] = fma2(h1v.x, wv.x, a1[r]);
                a1[r] = fma2(h1v.y, wv.y, a1[r]);
            }
        }
        asm volatile("cp.async.wait_group 0;");
        #pragma unroll 2
        for (int ch = 6; ch < 12; ch++) {
            int kk = ch * 4;
            ulonglong2 h0v = *(const ulonglong2*)(hb0 + kk);
            ulonglong2 h1v = *(const ulonglong2*)(hb1 + kk);
            #pragma unroll
            for (int r = 0; r < 24; r++) {
                ulonglong2 wv = *(const ulonglong2*)(wkb + r * HN + kk);
                a0[r] = fma2(h0v.x, wv.x, a0[r]);
                a0[r] = fma2(h0v.y, wv.y, a0[r]);
                a1[r] = fma2(h1v.x, wv.x, a1[r]);
                a1[r] = fma2(h1v.y, wv.y, a1[r]);
            }
        }

        #pragma unroll
        for (int r = 0; r < 24; r++) {
            P[(kg * 24 + r) * 65 + lane]      = unpack_sum(a0[r]);
            P[(kg * 24 + r) * 65 + lane + 32] = unpack_sum(a1[r]);
        }
        __syncthreads();

        // cell update
        float hv0, hv1 = 0.f;
        {
            bool valid = (t < sent_s[be0]);
            float g4[4];
            #pragma unroll
            for (int g = 0; g < 4; g++) {
                int r = g * 6 + je0;
                float sum = 0.f;
                #pragma unroll
                for (int k8 = 0; k8 < 8; k8++) sum += P[(k8 * 24 + r) * 65 + be0];
                g4[g] = sum + (valid ? xp0[g] : bias_s[r]);
            }
            float ig = sig_fast(g4[0]), fg = sig_fast(g4[1]);
            float cg = tanh_fast(g4[2]), og = sig_fast(g4[3]);
            c0r = fg * c0r + ig * cg;
            hv0 = og * tanh_fast(c0r);
            g_h[((dir * 2 + (p ^ 1)) * BN + be0) * HN + j0 + je0] = hv0;
        }
        if (p1v) {
            bool valid = (t < sent_s[be1]);
            float g4[4];
            #pragma unroll
            for (int g = 0; g < 4; g++) {
                int r = g * 6 + je1;
                float sum = 0.f;
                #pragma unroll
                for (int k8 = 0; k8 < 8; k8++) sum += P[(k8 * 24 + r) * 65 + be1];
                g4[g] = sum + (valid ? xp1[g] : bias_s[r]);
            }
            float ig = sig_fast(g4[0]), fg = sig_fast(g4[1]);
            float cg = tanh_fast(g4[2]), og = sig_fast(g4[3]);
            c1r = fg * c1r + ig * cg;
            hv1 = og * tanh_fast(c1r);
            g_h[((dir * 2 + (p ^ 1)) * BN + be1) * HN + j0 + je1] = hv1;
        }
        __syncthreads();

        // arrive, then hide g_lstm stores under other blocks' arrival
        if (tid == 0) {
            __threadfence();
            unsigned tk = atomicAdd(&g_bar_cnt2[dir], 1u);
            if (tk == 63) { g_bar_cnt2[dir] = 0; __threadfence(); g_bar_gen2[dir] = my_gen + 1; }
        }
        g_lstm[((size_t)be0 * SN + t) * (2 * HN) + dir * HN + j0 + je0] = hv0;
        if (p1v) g_lstm[((size_t)be1 * SN + t) * (2 * HN) + dir * HN + j0 + je1] = hv1;
        if (tid == 0) {
            while (g_bar_gen2[dir] <= my_gen) { __nanosleep(32); }
            __threadfence();
        }
        __syncthreads();
        my_gen++;
    }
}

// ---------------- K4: output linear (Wlin cached in smem, 16 rows/block) -------
__global__ void __launch_bounds__(256) out_kernel(
    const float* __restrict__ Wlin, const float* __restrict__ blin,
    float* __restrict__ out)
{
    extern __shared__ float Wl[];   // 22*768 floats
    int tid = threadIdx.x;
    int lane = tid & 31, w = tid >> 5;
    for (int idx = tid; idx < TN * 768; idx += 256) Wl[idx] = Wlin[idx];
    __syncthreads();

    int base = blockIdx.x * 16;
    #pragma unroll
    for (int rr = 0; rr < 2; rr++) {
        int row = base + w * 2 + rr;
        const float* src = g_lstm + (size_t)row * 768;
        float rs[24];
        #pragma unroll
        for (int i = 0; i < 24; i++) rs[i] = src[lane + 32 * i];
        for (int o = 0; o < TN; o++) {
            const float* wr = &Wl[o * 768];
            float s = 0.f;
            #pragma unroll
            for (int i = 0; i < 24; i++) s += rs[i] * wr[lane + 32 * i];
            #pragma unroll
            for (int off = 16; off; off >>= 1) s += __shfl_down_sync(0xffffffffu, s, off);
            if (lane == 0) out[(size_t)row * TN + o] = s + blin[o];
        }
    }
}

// ---------------- launch --------------------------------------------------------
extern "C" void kernel_launch(void* const* d_in, const int* in_sizes, int n_in,
                              void* d_out, int out_size) {
    const float* hs   = (const float*)d_in[0];
    const float* h0   = (const float*)d_in[1];
    const float* c0   = (const float*)d_in[2];
    const float* Wihf = (const float*)d_in[3];
    const float* Whhf = (const float*)d_in[4];
    const float* bihf = (const float*)d_in[5];
    const float* bhhf = (const float*)d_in[6];
    const float* Wihb = (const float*)d_in[7];
    const float* Whhb = (const float*)d_in[8];
    const float* bihb = (const float*)d_in[9];
    const float* bhhb = (const float*)d_in[10];
    const float* Wlin = (const float*)d_in[11];
    const float* blin = (const float*)d_in[12];
    const void*  sid  = d_in[13];
    const void*  msk  = d_in[14];

    meta_kernel<<<BN, 256>>>(sid, msk);
    gather_kernel<<<dim3(SN, BN), 192>>>(hs, sid);
    proj_kernel<<<dim3(GN / 64, SN / 128, 2 * BN), 256>>>(Wihf, Wihb, bihf, bhhf, bihb, bhhb);

    const int rec_smem = (9216 + 26624 + 12480 + 24 + 64) * 4;
    cudaFuncSetAttribute(lstm_kernel, cudaFuncAttributeMaxDynamicSharedMemorySize, rec_smem);
    lstm_kernel<<<NBLK_REC, REC_THREADS, rec_smem>>>(Whhf, Whhb, bihf, bhhf, bihb, bhhb, h0, c0);

    const int out_smem = TN * 768 * 4;
    cudaFuncSetAttribute(out_kernel, cudaFuncAttributeMaxDynamicSharedMemorySize, out_smem);
    out_kernel<<<(BN * SN) / 16, 256, out_smem>>>(Wlin, blin, (float*)d_out);
}

// round 6
// speedup vs baseline: 1.2525x; 1.2525x over previous
#include <cuda_runtime.h>
#include <math.h>

#define BN 64
#define SN 512
#define DN 768
#define HN 384
#define GN 1536
#define TN 22

#define NBLK_REC 128
#define REC_THREADS 512

// ---------------- scratch (static device globals; zero-initialized) ---------
__device__ float g_embeds[BN * SN * DN];
__device__ float g_xg[2 * SN * BN * GN];                 // [dir][t][b][4H]
__device__ float g_lstm[BN * SN * 2 * HN];               // [b][t][2H]
__device__ float g_h[2 * 2 * BN * HN];                   // [dir][parity][b][H]
__device__ int   g_n[BN];
__device__ int   g_sent[BN];
__device__ int   g_last[BN];
__device__ unsigned g_bar_gen2[2];
__device__ unsigned g_bar_cnt2[2];

// ---------------- packed fp32x2 / fast math helpers ---------------------------
__device__ __forceinline__ unsigned long long fma2(unsigned long long a,
                                                   unsigned long long b,
                                                   unsigned long long c) {
    unsigned long long d;
    asm("fma.rn.f32x2 %0, %1, %2, %3;" : "=l"(d) : "l"(a), "l"(b), "l"(c));
    return d;
}
__device__ __forceinline__ float unpack_sum(unsigned long long v) {
    float lo, hi;
    asm("mov.b64 {%0, %1}, %2;" : "=f"(lo), "=f"(hi) : "l"(v));
    return lo + hi;
}
__device__ __forceinline__ float tanh_fast(float x) {
    float y;
    asm("tanh.approx.f32 %0, %1;" : "=f"(y) : "f"(x));
    return y;
}
__device__ __forceinline__ float sig_fast(float x) {
    return 0.5f * tanh_fast(0.5f * x) + 0.5f;
}

// ---------------- scoped atomics for the grid barrier --------------------------
__device__ __forceinline__ unsigned atom_add_release(unsigned* p, unsigned v) {
    unsigned old;
    asm volatile("atom.release.gpu.global.add.u32 %0, [%1], %2;"
                 : "=r"(old) : "l"(p), "r"(v) : "memory");
    return old;
}
__device__ __forceinline__ unsigned ld_acquire(unsigned* p) {
    unsigned v;
    asm volatile("ld.acquire.gpu.global.u32 %0, [%1];" : "=r"(v) : "l"(p) : "memory");
    return v;
}
__device__ __forceinline__ void st_relaxed_u32(unsigned* p, unsigned v) {
    asm volatile("st.relaxed.gpu.global.u32 [%0], %1;" :: "l"(p), "r"(v) : "memory");
}
__device__ __forceinline__ void st_release_u32(unsigned* p, unsigned v) {
    asm volatile("st.release.gpu.global.u32 [%0], %1;" :: "l"(p), "r"(v) : "memory");
}

// ---------------- index helpers -------------------------------------------------
__device__ __forceinline__ long long ld_idx(const void* p, int i, bool is64) {
    return is64 ? ((const long long*)p)[i] : (long long)((const int*)p)[i];
}
__device__ __forceinline__ bool detect_is64(const void* start_ids) {
    return ((const int*)start_ids)[1] == 0;
}

// ---------------- K0: per-batch metadata ----------------------------------------
__global__ void meta_kernel(const void* start_ids, const void* masks) {
    int b = blockIdx.x;
    int tid = threadIdx.x;
    bool is64 = detect_is64(start_ids);
    __shared__ int red[256];
    int cnt = 0, sm = 0;
    for (int t = tid; t < SN; t += 256) {
        long long sv = ld_idx(start_ids, b * SN + t, is64);
        long long mv = ld_idx(masks, b * SN + t, is64);
        cnt += (sv >= 0);
        sm += (int)mv;
    }
    red[tid] = cnt; __syncthreads();
    for (int o = 128; o > 0; o >>= 1) { if (tid < o) red[tid] += red[tid + o]; __syncthreads(); }
    int ntot = red[0]; __syncthreads();
    red[tid] = sm; __syncthreads();
    for (int o = 128; o > 0; o >>= 1) { if (tid < o) red[tid] += red[tid + o]; __syncthreads(); }
    int stot = red[0];
    if (tid == 0) {
        g_n[b] = ntot;
        g_sent[b] = stot;
        long long last = 0;
        if (ntot > 0) last = ld_idx(start_ids, b * SN + ntot - 1, is64);
        g_last[b] = (int)last;
    }
}

// ---------------- K1: align gather -----------------------------------------------
__global__ void gather_kernel(const float* __restrict__ hs, const void* __restrict__ start_ids) {
    int t = blockIdx.x, b = blockIdx.y;
    int sent = g_sent[b];
    if (t >= sent) return;
    bool is64 = detect_is64(start_ids);
    int n = g_n[b];
    long long idx;
    if (t == 0)      idx = 0;
    else if (t < n)  idx = ld_idx(start_ids, b * SN + t, is64) - 1;
    else if (t == n) idx = g_last[b];
    else             idx = 0;
    if (idx < 0) idx = 0;
    if (idx > SN - 1) idx = SN - 1;
    const float4* src = (const float4*)(hs + ((size_t)b * SN + (size_t)idx) * DN);
    float4* dst = (float4*)(g_embeds + ((size_t)b * SN + t) * DN);
    dst[threadIdx.x] = src[threadIdx.x];
}

// ---------------- K2: input projection GEMM (f32x2, cp.async, 2 blocks/SM) -------
__global__ void __launch_bounds__(256, 2) proj_kernel(
    const float* __restrict__ Wf, const float* __restrict__ Wb,
    const float* __restrict__ bihf, const float* __restrict__ bhhf,
    const float* __restrict__ bihb, const float* __restrict__ bhhb)
{
    int b = blockIdx.z & 63;
    int dir = blockIdx.z >> 6;
    int sent = g_sent[b];
    int t0 = blockIdx.y * 128;
    if (t0 >= sent) return;
    int n0 = blockIdx.x * 64;

    const float* W   = dir ? Wb   : Wf;
    const float* bih = dir ? bihb : bihf;
    const float* bhh = dir ? bhhb : bhhf;

    __shared__ float As[2][128][20];
    __shared__ float Bs[2][64][20];

    int tid = threadIdx.x;
    int tx = tid & 15, ty = tid >> 4;
    int bsw = ((tx >> 3) & 1) << 2;

    unsigned long long acc[8][4];
    #pragma unroll
    for (int i = 0; i < 8; i++)
        #pragma unroll
        for (int j = 0; j < 4; j++) acc[i][j] = 0ull;

    #define PROJ_FILL(stg, kt)                                                           \
        do {                                                                             \
            _Pragma("unroll")                                                            \
            for (int f = 0; f < 2; f++) {                                                \
                int lin = tid + f * 256;                                                 \
                int row = lin >> 2;                                                      \
                int c = (lin & 3) * 4;                                                   \
                unsigned sa = (unsigned)__cvta_generic_to_shared(&As[stg][row][c]);      \
                const float* ga = &g_embeds[((size_t)b * SN + t0 + row) * DN + (kt) + c];\
                asm volatile("cp.async.ca.shared.global [%0], [%1], 16;" :: "r"(sa), "l"(ga)); \
            }                                                                            \
            {                                                                            \
                int row = tid >> 2;                                                      \
                int c = (tid & 3) * 4;                                                   \
                int cs = c ^ (((row >> 3) & 1) << 2);                                    \
                unsigned sb = (unsigned)__cvta_generic_to_shared(&Bs[stg][row][cs]);     \
                const float* gb = &W[(size_t)(n0 + row) * DN + (kt) + c];                \
                asm volatile("cp.async.ca.shared.global [%0], [%1], 16;" :: "r"(sb), "l"(gb)); \
            }                                                                            \
            asm volatile("cp.async.commit_group;");                                      \
        } while (0)

    PROJ_FILL(0, 0);
    int st = 0;
    for (int kt = 0; kt < DN; kt += 16) {
        if (kt + 16 < DN) {
            PROJ_FILL(st ^ 1, kt + 16);
            asm volatile("cp.async.wait_group 1;");
        } else {
            asm volatile("cp.async.wait_group 0;");
        }
        __syncthreads();

        #pragma unroll
        for (int k = 0; k < 16; k += 4) {
            unsigned long long b0[4], b1[4];
            #pragma unroll
            for (int j = 0; j < 4; j++) {
                ulonglong2 v = *(const ulonglong2*)&Bs[st][tx + j * 16][k ^ bsw];
                b0[j] = v.x; b1[j] = v.y;
            }
            #pragma unroll
            for (int i = 0; i < 8; i++) {
                ulonglong2 av = *(const ulonglong2*)&As[st][ty + i * 16][k];
                #pragma unroll
                for (int j = 0; j < 4; j++) {
                    acc[i][j] = fma2(av.x, b0[j], acc[i][j]);
                    acc[i][j] = fma2(av.y, b1[j], acc[i][j]);
                }
            }
        }
        __syncthreads();
        st ^= 1;
    }
    #undef PROJ_FILL

    float bsj[4];
    #pragma unroll
    for (int j = 0; j < 4; j++) {
        int n = n0 + tx + j * 16;
        bsj[j] = bih[n] + bhh[n];
    }
    #pragma unroll
    for (int i = 0; i < 8; i++) {
        int t = t0 + ty + i * 16;
        if (t < sent) {
            float* dst = &g_xg[((size_t)(dir * SN + t) * BN + b) * GN + n0 + tx];
            #pragma unroll
            for (int j = 0; j < 4; j++)
                dst[j * 16] = unpack_sum(acc[i][j]) + bsj[j];
        }
    }
}

// ---------------- K3: persistent bidirectional LSTM recurrence --------------------
// 128 blocks (64/dir), 512 threads. GEMV: ks=tid>>7 (k-split 4, 96 k each),
// rg=(tid&127)>>5 (4 row-groups of 6 rows), bp=tid&31 (batches bp, bp+32).
// Cell (tid<384): je=tid/64, be=tid%64. P transposed [be][96] pad 97 (conflict-free).
__global__ void __launch_bounds__(REC_THREADS, 1) lstm_kernel(
    const float* __restrict__ Whhf, const float* __restrict__ Whhb,
    const float* __restrict__ bihf, const float* __restrict__ bhhf,
    const float* __restrict__ bihb, const float* __restrict__ bhhb,
    const float* __restrict__ h0, const float* __restrict__ c0)
{
    extern __shared__ float sm_[];
    float* ws     = sm_;                         // 24*384 = 9216
    float* hs     = sm_ + 9216;                  // 64*388 = 24832 (97 mod 32 = 1 in 16B units)
    float* P      = sm_ + 9216 + 24832;          // 64*97  = 6208
    float* bias_s = P + 6208;                    // 24
    int*   sent_s = (int*)(bias_s + 24);         // 64

    int tid = threadIdx.x;
    int blk = blockIdx.x;
    int dir = blk >> 6;
    int j0 = (blk & 63) * 6;

    const float* Whh = dir ? Whhb : Whhf;
    const float* bih = dir ? bihb : bihf;
    const float* bhh = dir ? bhhb : bhhf;

    for (int idx = tid; idx < 24 * HN; idx += REC_THREADS) {
        int r = idx / HN, k = idx % HN;
        int wrow = (r / 6) * HN + j0 + (r % 6);
        ws[r * HN + k] = Whh[(size_t)wrow * HN + k];
    }
    if (tid < 24) {
        int ng = (tid / 6) * HN + j0 + (tid % 6);
        bias_s[tid] = bih[ng] + bhh[ng];
    }
    if (tid < BN) sent_s[tid] = g_sent[tid];

    // cell ownership
    bool cellv = (tid < 384);
    int je = tid >> 6;            // 0..5 for tid<384 (warp-uniform)
    int be = tid & 63;
    float creg = 0.f;
    if (cellv) {
        g_h[((dir * 2 + 0) * BN + be) * HN + j0 + je] =
            h0[((size_t)dir * BN + be) * HN + j0 + je];
        creg = c0[((size_t)dir * BN + be) * HN + j0 + je];
    }

    // GEMV coords
    int ks = tid >> 7;            // 0..3, warp-uniform
    int rg = (tid & 127) >> 5;    // 0..3, warp-uniform
    int bp = tid & 31;
    int kbase = ks * 96;
    const float* hb0 = &hs[bp * 388 + kbase];
    const float* hb1 = &hs[(bp + 32) * 388 + kbase];
    const float* wkb = &ws[(rg * 6) * HN + kbase];

    // staging coords: thread stages 16 chunks of 16B
    int sb0 = tid / 96;           // 0..5 (then +4f... no: +? see loop)
    int skk = (tid % 96) * 4;

    // stateless barrier: read absolute generation before any arrival
    unsigned my_gen = 0;
    if (tid == 0) my_gen = ld_acquire(&g_bar_gen2[dir]);
    __syncthreads();

    // initial barrier (h0 published)
    if (tid == 0) {
        unsigned old = atom_add_release(&g_bar_cnt2[dir], 1u);
        if (old == 63) {
            st_relaxed_u32(&g_bar_cnt2[dir], 0u);
            st_release_u32(&g_bar_gen2[dir], my_gen + 1);
        } else {
            while (ld_acquire(&g_bar_gen2[dir]) == my_gen) { }
        }
        my_gen++;
    }
    __syncthreads();

    for (int s = 0; s < SN; s++) {
        int p = s & 1;
        int t = dir ? (SN - 1 - s) : s;

        // stage previous h into smem via cp.async (block-wide, coalesced)
        const float* hsrc = g_h + (size_t)(dir * 2 + p) * BN * HN;
        {
            // 6144 16B-chunks, 512 threads -> 12 per thread
            #pragma unroll
            for (int f = 0; f < 12; f++) {
                int idx = tid + f * REC_THREADS;
                int b2 = idx / 96;
                int kk = (idx % 96) * 4;
                unsigned sd = (unsigned)__cvta_generic_to_shared(&hs[b2 * 388 + kk]);
                const float* gsrc = hsrc + (size_t)b2 * HN + kk;
                asm volatile("cp.async.ca.shared.global [%0], [%1], 16;" :: "r"(sd), "l"(gsrc));
            }
            asm volatile("cp.async.commit_group;");
        }

        // prefetch xg for the cell while staging lands
        float xp[4];
        if (cellv) {
            const float* xb = &g_xg[((size_t)(dir * SN + t) * BN + be) * GN + j0 + je];
            #pragma unroll
            for (int g = 0; g < 4; g++) xp[g] = xb[g * HN];
        }

        asm volatile("cp.async.wait_group 0;");
        __syncthreads();

        // GEMV: 6 rows x 2 batches x 96 k per thread, packed f32x2
        {
            unsigned long long a0[6], a1[6];
            #pragma unroll
            for (int r = 0; r < 6; r++) { a0[r] = 0ull; a1[r] = 0ull; }
            #pragma unroll 4
            for (int kk = 0; kk < 96; kk += 4) {
                ulonglong2 h0v = *(const ulonglong2*)(hb0 + kk);
                ulonglong2 h1v = *(const ulonglong2*)(hb1 + kk);
                #pragma unroll
                for (int r = 0; r < 6; r++) {
                    ulonglong2 wv = *(const ulonglong2*)(wkb + r * HN + kk);
                    a0[r] = fma2(h0v.x, wv.x, a0[r]);
                    a0[r] = fma2(h0v.y, wv.y, a0[r]);
                    a1[r] = fma2(h1v.x, wv.x, a1[r]);
                    a1[r] = fma2(h1v.y, wv.y, a1[r]);
                }
            }
            #pragma unroll
            for (int r = 0; r < 6; r++) {
                int rr = ks * 24 + rg * 6 + r;
                P[bp * 97 + rr]        = unpack_sum(a0[r]);
                P[(bp + 32) * 97 + rr] = unpack_sum(a1[r]);
            }
        }
        __syncthreads();

        // cell update (conflict-free P reads: stride 97 == 1 mod 32, be = lane-consecutive)
        float hv = 0.f;
        if (cellv) {
            bool valid = (t < sent_s[be]);
            const float* Pr = &P[be * 97];
            float g4[4];
            #pragma unroll
            for (int g = 0; g < 4; g++) {
                int r = g * 6 + je;
                float sum = Pr[r] + Pr[24 + r] + Pr[48 + r] + Pr[72 + r];
                g4[g] = sum + (valid ? xp[g] : bias_s[r]);
            }
            float ig = sig_fast(g4[0]), fg = sig_fast(g4[1]);
            float cg = tanh_fast(g4[2]), og = sig_fast(g4[3]);
            creg = fg * creg + ig * cg;
            hv = og * tanh_fast(creg);
            g_h[((dir * 2 + (p ^ 1)) * BN + be) * HN + j0 + je] = hv;
        }
        __syncthreads();

        // arrive (release publishes this block's h stores), hide g_lstm store, then wait
        if (tid == 0) {
            unsigned old = atom_add_release(&g_bar_cnt2[dir], 1u);
            if (old == 63) {
                st_relaxed_u32(&g_bar_cnt2[dir], 0u);
                st_release_u32(&g_bar_gen2[dir], my_gen + 1);
            }
        }
        if (cellv)
            g_lstm[((size_t)be * SN + t) * (2 * HN) + dir * HN + j0 + je] = hv;
        if (tid == 0) {
            while (ld_acquire(&g_bar_gen2[dir]) == my_gen) { }
            my_gen++;
        }
        __syncthreads();
    }
}

// ---------------- K4: output linear (Wlin cached in smem, 16 rows/block) ----------
__global__ void __launch_bounds__(256) out_kernel(
    const float* __restrict__ Wlin, const float* __restrict__ blin,
    float* __restrict__ out)
{
    extern __shared__ float Wl[];   // 22*768 floats
    int tid = threadIdx.x;
    int lane = tid & 31, w = tid >> 5;
    for (int idx = tid; idx < TN * 768; idx += 256) Wl[idx] = Wlin[idx];
    __syncthreads();

    int base = blockIdx.x * 16;
    #pragma unroll
    for (int rr = 0; rr < 2; rr++) {
        int row = base + w * 2 + rr;
        const float* src = g_lstm + (size_t)row * 768;
        float rs[24];
        #pragma unroll
        for (int i = 0; i < 24; i++) rs[i] = src[lane + 32 * i];
        for (int o = 0; o < TN; o++) {
            const float* wr = &Wl[o * 768];
            float s = 0.f;
            #pragma unroll
            for (int i = 0; i < 24; i++) s += rs[i] * wr[lane + 32 * i];
            #pragma unroll
            for (int off = 16; off; off >>= 1) s += __shfl_down_sync(0xffffffffu, s, off);
            if (lane == 0) out[(size_t)row * TN + o] = s + blin[o];
        }
    }
}

// ---------------- launch -----------------------------------------------------------
extern "C" void kernel_launch(void* const* d_in, const int* in_sizes, int n_in,
                              void* d_out, int out_size) {
    const float* hs   = (const float*)d_in[0];
    const float* h0   = (const float*)d_in[1];
    const float* c0   = (const float*)d_in[2];
    const float* Wihf = (const float*)d_in[3];
    const float* Whhf = (const float*)d_in[4];
    const float* bihf = (const float*)d_in[5];
    const float* bhhf = (const float*)d_in[6];
    const float* Wihb = (const float*)d_in[7];
    const float* Whhb = (const float*)d_in[8];
    const float* bihb = (const float*)d_in[9];
    const float* bhhb = (const float*)d_in[10];
    const float* Wlin = (const float*)d_in[11];
    const float* blin = (const float*)d_in[12];
    const void*  sid  = d_in[13];
    const void*  msk  = d_in[14];

    meta_kernel<<<BN, 256>>>(sid, msk);
    gather_kernel<<<dim3(SN, BN), 192>>>(hs, sid);
    proj_kernel<<<dim3(GN / 64, SN / 128, 2 * BN), 256>>>(Wihf, Wihb, bihf, bhhf, bihb, bhhb);

    const int rec_smem = (9216 + 24832 + 6208 + 24 + 64) * 4;
    cudaFuncSetAttribute(lstm_kernel, cudaFuncAttributeMaxDynamicSharedMemorySize, rec_smem);
    lstm_kernel<<<NBLK_REC, REC_THREADS, rec_smem>>>(Whhf, Whhb, bihf, bhhf, bihb, bhhb, h0, c0);

    const int out_smem = TN * 768 * 4;
    cudaFuncSetAttribute(out_kernel, cudaFuncAttributeMaxDynamicSharedMemorySize, out_smem);
    out_kernel<<<(BN * SN) / 16, 256, out_smem>>>(Wlin, blin, (float*)d_out);
}

// round 7
// speedup vs baseline: 1.4025x; 1.1198x over previous
#include <cuda_runtime.h>
#include <math.h>

#define BN 64
#define SN 512
#define DN 768
#define HN 384
#define GN 1536
#define TN 22

#define NBLK_REC 128
#define REC_THREADS 512

// ---------------- scratch (static device globals; zero-initialized) ---------
__device__ float g_embeds[BN * SN * DN];
__device__ float g_xg[2 * SN * BN * GN];                 // [dir][t][b][4H]
__device__ float g_lstm[BN * SN * 2 * HN];               // [b][t][2H]
__device__ float g_h[2 * 2 * BN * HN];                   // [dir][parity][b][H]
__device__ int   g_n[BN];
__device__ int   g_sent[BN];
__device__ int   g_last[BN];
__device__ unsigned g_bcnt[8];                           // monotonic, per (dir,bgroup)
__device__ unsigned g_bgen[8];

// ---------------- packed fp32x2 / fast math helpers ---------------------------
__device__ __forceinline__ unsigned long long fma2(unsigned long long a,
                                                   unsigned long long b,
                                                   unsigned long long c) {
    unsigned long long d;
    asm("fma.rn.f32x2 %0, %1, %2, %3;" : "=l"(d) : "l"(a), "l"(b), "l"(c));
    return d;
}
__device__ __forceinline__ float unpack_sum(unsigned long long v) {
    float lo, hi;
    asm("mov.b64 {%0, %1}, %2;" : "=f"(lo), "=f"(hi) : "l"(v));
    return lo + hi;
}
__device__ __forceinline__ float tanh_fast(float x) {
    float y;
    asm("tanh.approx.f32 %0, %1;" : "=f"(y) : "f"(x));
    return y;
}
__device__ __forceinline__ float sig_fast(float x) {
    return 0.5f * tanh_fast(0.5f * x) + 0.5f;
}

// ---------------- scoped atomics for the grid barrier --------------------------
__device__ __forceinline__ unsigned atom_add_acqrel(unsigned* p, unsigned v) {
    unsigned old;
    asm volatile("atom.acq_rel.gpu.global.add.u32 %0, [%1], %2;"
                 : "=r"(old) : "l"(p), "r"(v) : "memory");
    return old;
}
__device__ __forceinline__ unsigned ld_acquire(unsigned* p) {
    unsigned v;
    asm volatile("ld.acquire.gpu.global.u32 %0, [%1];" : "=r"(v) : "l"(p) : "memory");
    return v;
}
__device__ __forceinline__ void st_release_u32(unsigned* p, unsigned v) {
    asm volatile("st.release.gpu.global.u32 [%0], %1;" :: "l"(p), "r"(v) : "memory");
}

// ---------------- index helpers -------------------------------------------------
__device__ __forceinline__ long long ld_idx(const void* p, int i, bool is64) {
    return is64 ? ((const long long*)p)[i] : (long long)((const int*)p)[i];
}
__device__ __forceinline__ bool detect_is64(const void* start_ids) {
    return ((const int*)start_ids)[1] == 0;
}

// ---------------- K0: per-batch metadata ----------------------------------------
__global__ void meta_kernel(const void* start_ids, const void* masks) {
    int b = blockIdx.x;
    int tid = threadIdx.x;
    bool is64 = detect_is64(start_ids);
    __shared__ int red[256];
    int cnt = 0, sm = 0;
    for (int t = tid; t < SN; t += 256) {
        long long sv = ld_idx(start_ids, b * SN + t, is64);
        long long mv = ld_idx(masks, b * SN + t, is64);
        cnt += (sv >= 0);
        sm += (int)mv;
    }
    red[tid] = cnt; __syncthreads();
    for (int o = 128; o > 0; o >>= 1) { if (tid < o) red[tid] += red[tid + o]; __syncthreads(); }
    int ntot = red[0]; __syncthreads();
    red[tid] = sm; __syncthreads();
    for (int o = 128; o > 0; o >>= 1) { if (tid < o) red[tid] += red[tid + o]; __syncthreads(); }
    int stot = red[0];
    if (tid == 0) {
        g_n[b] = ntot;
        g_sent[b] = stot;
        long long last = 0;
        if (ntot > 0) last = ld_idx(start_ids, b * SN + ntot - 1, is64);
        g_last[b] = (int)last;
    }
}

// ---------------- K1: align gather -----------------------------------------------
__global__ void gather_kernel(const float* __restrict__ hs, const void* __restrict__ start_ids) {
    int t = blockIdx.x, b = blockIdx.y;
    int sent = g_sent[b];
    if (t >= sent) return;
    bool is64 = detect_is64(start_ids);
    int n = g_n[b];
    long long idx;
    if (t == 0)      idx = 0;
    else if (t < n)  idx = ld_idx(start_ids, b * SN + t, is64) - 1;
    else if (t == n) idx = g_last[b];
    else             idx = 0;
    if (idx < 0) idx = 0;
    if (idx > SN - 1) idx = SN - 1;
    const float4* src = (const float4*)(hs + ((size_t)b * SN + (size_t)idx) * DN);
    float4* dst = (float4*)(g_embeds + ((size_t)b * SN + t) * DN);
    dst[threadIdx.x] = src[threadIdx.x];
}

// ---------------- K2: input projection GEMM (f32x2, cp.async, 2 blocks/SM) -------
__global__ void __launch_bounds__(256, 2) proj_kernel(
    const float* __restrict__ Wf, const float* __restrict__ Wb,
    const float* __restrict__ bihf, const float* __restrict__ bhhf,
    const float* __restrict__ bihb, const float* __restrict__ bhhb)
{
    int b = blockIdx.z & 63;
    int dir = blockIdx.z >> 6;
    int sent = g_sent[b];
    int t0 = blockIdx.y * 128;
    if (t0 >= sent) return;
    int n0 = blockIdx.x * 64;

    const float* W   = dir ? Wb   : Wf;
    const float* bih = dir ? bihb : bihf;
    const float* bhh = dir ? bhhb : bhhf;

    __shared__ float As[2][128][20];
    __shared__ float Bs[2][64][20];

    int tid = threadIdx.x;
    int tx = tid & 15, ty = tid >> 4;
    int bsw = ((tx >> 3) & 1) << 2;

    unsigned long long acc[8][4];
    #pragma unroll
    for (int i = 0; i < 8; i++)
        #pragma unroll
        for (int j = 0; j < 4; j++) acc[i][j] = 0ull;

    #define PROJ_FILL(stg, kt)                                                           \
        do {                                                                             \
            _Pragma("unroll")                                                            \
            for (int f = 0; f < 2; f++) {                                                \
                int lin = tid + f * 256;                                                 \
                int row = lin >> 2;                                                      \
                int c = (lin & 3) * 4;                                                   \
                unsigned sa = (unsigned)__cvta_generic_to_shared(&As[stg][row][c]);      \
                const float* ga = &g_embeds[((size_t)b * SN + t0 + row) * DN + (kt) + c];\
                asm volatile("cp.async.ca.shared.global [%0], [%1], 16;" :: "r"(sa), "l"(ga)); \
            }                                                                            \
            {                                                                            \
                int row = tid >> 2;                                                      \
                int c = (tid & 3) * 4;                                                   \
                int cs = c ^ (((row >> 3) & 1) << 2);                                    \
                unsigned sb = (unsigned)__cvta_generic_to_shared(&Bs[stg][row][cs]);     \
                const float* gb = &W[(size_t)(n0 + row) * DN + (kt) + c];                \
                asm volatile("cp.async.ca.shared.global [%0], [%1], 16;" :: "r"(sb), "l"(gb)); \
            }                                                                            \
            asm volatile("cp.async.commit_group;");                                      \
        } while (0)

    PROJ_FILL(0, 0);
    int st = 0;
    for (int kt = 0; kt < DN; kt += 16) {
        if (kt + 16 < DN) {
            PROJ_FILL(st ^ 1, kt + 16);
            asm volatile("cp.async.wait_group 1;");
        } else {
            asm volatile("cp.async.wait_group 0;");
        }
        __syncthreads();

        #pragma unroll
        for (int k = 0; k < 16; k += 4) {
            unsigned long long b0[4], b1[4];
            #pragma unroll
            for (int j = 0; j < 4; j++) {
                ulonglong2 v = *(const ulonglong2*)&Bs[st][tx + j * 16][k ^ bsw];
                b0[j] = v.x; b1[j] = v.y;
            }
            #pragma unroll
            for (int i = 0; i < 8; i++) {
                ulonglong2 av = *(const ulonglong2*)&As[st][ty + i * 16][k];
                #pragma unroll
                for (int j = 0; j < 4; j++) {
                    acc[i][j] = fma2(av.x, b0[j], acc[i][j]);
                    acc[i][j] = fma2(av.y, b1[j], acc[i][j]);
                }
            }
        }
        __syncthreads();
        st ^= 1;
    }
    #undef PROJ_FILL

    float bsj[4];
    #pragma unroll
    for (int j = 0; j < 4; j++) {
        int n = n0 + tx + j * 16;
        bsj[j] = bih[n] + bhh[n];
    }
    #pragma unroll
    for (int i = 0; i < 8; i++) {
        int t = t0 + ty + i * 16;
        if (t < sent) {
            float* dst = &g_xg[((size_t)(dir * SN + t) * BN + b) * GN + n0 + tx];
            #pragma unroll
            for (int j = 0; j < 4; j++)
                dst[j * 16] = unpack_sum(acc[i][j]) + bsj[j];
        }
    }
}

// ---------------- K3: persistent bidirectional LSTM recurrence --------------------
// 128 blocks: dir = blk>>6; g6 = blk&63; bg = g6>>4 (batch group, 16 batches);
// hsl = g6&15 (hidden slice, 24 units = 96 gate rows). Whh slice 96x384 in smem.
// Warps: w = tid>>5; ks = w>>2 (k-split 4, 96 k); rg = w&3. Lane: bq = l>>3, rs = l&7.
// Thread GEMV tile: 3 rows (rg*24 + rs*3 ..) x 4 batches (bq*4 ..) x 96 k (f32x2).
// Barrier scope: 16 blocks sharing (dir,bg) -> 8 independent monotonic barriers.
__global__ void __launch_bounds__(REC_THREADS, 1) lstm_kernel(
    const float* __restrict__ Whhf, const float* __restrict__ Whhb,
    const float* __restrict__ bihf, const float* __restrict__ bhhf,
    const float* __restrict__ bihb, const float* __restrict__ bhhb,
    const float* __restrict__ h0, const float* __restrict__ c0)
{
    extern __shared__ float sm_[];
    float* ws     = sm_;                          // 96*388  = 37248
    float* hsm    = sm_ + 37248;                  // 16*388  = 6208
    float* P      = sm_ + 37248 + 6208;           // 384*17  = 6528
    float* bias_s = P + 6528;                     // 96
    int*   sent_s = (int*)(bias_s + 96);          // 16

    int tid = threadIdx.x;
    int blk = blockIdx.x;
    int dir = blk >> 6;
    int g6  = blk & 63;
    int bg  = g6 >> 4;            // batch group (16 batches)
    int u0  = (g6 & 15) * 24;     // first hidden unit of slice

    const float* Whh = dir ? Whhb : Whhf;
    const float* bih = dir ? bihb : bihf;
    const float* bhh = dir ? bhhb : bhhf;

    // load Whh slice: local row r = gate*24 + u  ->  global row gate*HN + u0 + u
    for (int idx = tid; idx < 96 * HN; idx += REC_THREADS) {
        int r = idx / HN, k = idx % HN;
        int grow = (r / 24) * HN + u0 + (r % 24);
        ws[r * 388 + k] = Whh[(size_t)grow * HN + k];
    }
    if (tid < 96) {
        int grow = (tid / 24) * HN + u0 + (tid % 24);
        bias_s[tid] = bih[grow] + bhh[grow];
    }
    if (tid < 16) sent_s[tid] = g_sent[bg * 16 + tid];

    // cell ownership: tid < 384: lb = tid/24 (0..15), u = tid%24
    bool cellv = (tid < 384);
    int lb = tid / 24, u = tid % 24;
    int gb = bg * 16 + lb;                         // global batch
    int gj = u0 + u;                               // global hidden unit
    float creg = 0.f;
    if (cellv) {
        g_h[((dir * 2 + 0) * BN + gb) * HN + gj] = h0[((size_t)dir * BN + gb) * HN + gj];
        creg = c0[((size_t)dir * BN + gb) * HN + gj];
    }

    // GEMV coords
    int w    = tid >> 5;
    int ks   = w >> 2;             // 0..3 (warp-uniform)
    int rg   = w & 3;              // 0..3 (warp-uniform)
    int lane = tid & 31;
    int bq   = lane >> 3;          // 0..3
    int rs   = lane & 7;           // 0..7
    int kbase = ks * 96;
    int r0 = rg * 24 + rs * 3;
    const float* wr0 = &ws[(r0 + 0) * 388 + kbase];
    const float* wr1 = &ws[(r0 + 1) * 388 + kbase];
    const float* wr2 = &ws[(r0 + 2) * 388 + kbase];

    // staging coords: warp (ks, rg) stages h[b = rg*4..+4][k = ks*96..+96]
    // 96 chunks of 16B -> 3 per lane
    int gid = dir * 4 + bg;

    // barrier init: absolute generation (replay-safe, monotonic counters)
    unsigned my_gen = 0;
    if (tid == 0) my_gen = ld_acquire(&g_bgen[gid]);
    __syncthreads();

    // initial barrier: h0 slices published by all 16 blocks of this group
    if (tid == 0) {
        __threadfence();
        unsigned old = atom_add_acqrel(&g_bcnt[gid], 1u);
        if (((old + 1) & 15u) == 0u) {
            st_release_u32(&g_bgen[gid], my_gen + 1);
        } else {
            while (ld_acquire(&g_bgen[gid]) == my_gen) { }
        }
        my_gen++;
    }
    __syncthreads();

    for (int s = 0; s < SN; s++) {
        int p = s & 1;
        int t = dir ? (SN - 1 - s) : s;

        // prefetch xg for the cell (hidden under staging)
        float xp[4];
        if (cellv) {
            const float* xb = &g_xg[((size_t)(dir * SN + t) * BN + gb) * GN + gj];
            #pragma unroll
            for (int g = 0; g < 4; g++) xp[g] = xb[g * HN];
        }

        // stage h slice via cp.async.cg (L2-only; data produced by other blocks)
        {
            const float* hsrc = g_h + (size_t)((dir * 2 + p) * BN + bg * 16) * HN;
            #pragma unroll
            for (int c = 0; c < 3; c++) {
                int idx = lane + c * 32;           // 0..95
                int sb = rg * 4 + idx / 24;        // batch 0..15
                int kk = (idx % 24) * 4;
                unsigned sd = (unsigned)__cvta_generic_to_shared(&hsm[sb * 388 + kbase + kk]);
                const float* gsrc = hsrc + (size_t)sb * HN + kbase + kk;
                asm volatile("cp.async.cg.shared.global [%0], [%1], 16;" :: "r"(sd), "l"(gsrc));
            }
            asm volatile("cp.async.commit_group;");
            asm volatile("cp.async.wait_group 0;");
        }
        // sync only the 128 threads of this ks-group (warps 4ks..4ks+3 are contiguous)
        asm volatile("bar.sync %0, 128;" :: "r"(1 + ks) : "memory");

        // GEMV: 3 rows x 4 batches x 96 k, packed f32x2 (all smem loads 1 wavefront)
        {
            unsigned long long acc[3][4];
            #pragma unroll
            for (int i = 0; i < 3; i++)
                #pragma unroll
                for (int j = 0; j < 4; j++) acc[i][j] = 0ull;

            #pragma unroll 4
            for (int kk = 0; kk < 96; kk += 4) {
                ulonglong2 hv0 = *(const ulonglong2*)&hsm[(bq * 4 + 0) * 388 + kbase + kk];
                ulonglong2 hv1 = *(const ulonglong2*)&hsm[(bq * 4 + 1) * 388 + kbase + kk];
                ulonglong2 hv2 = *(const ulonglong2*)&hsm[(bq * 4 + 2) * 388 + kbase + kk];
                ulonglong2 hv3 = *(const ulonglong2*)&hsm[(bq * 4 + 3) * 388 + kbase + kk];
                ulonglong2 w0 = *(const ulonglong2*)(wr0 + kk);
                ulonglong2 w1 = *(const ulonglong2*)(wr1 + kk);
                ulonglong2 w2 = *(const ulonglong2*)(wr2 + kk);
                acc[0][0] = fma2(hv0.x, w0.x, acc[0][0]); acc[0][0] = fma2(hv0.y, w0.y, acc[0][0]);
                acc[0][1] = fma2(hv1.x, w0.x, acc[0][1]); acc[0][1] = fma2(hv1.y, w0.y, acc[0][1]);
                acc[0][2] = fma2(hv2.x, w0.x, acc[0][2]); acc[0][2] = fma2(hv2.y, w0.y, acc[0][2]);
                acc[0][3] = fma2(hv3.x, w0.x, acc[0][3]); acc[0][3] = fma2(hv3.y, w0.y, acc[0][3]);
                acc[1][0] = fma2(hv0.x, w1.x, acc[1][0]); acc[1][0] = fma2(hv0.y, w1.y, acc[1][0]);
                acc[1][1] = fma2(hv1.x, w1.x, acc[1][1]); acc[1][1] = fma2(hv1.y, w1.y, acc[1][1]);
                acc[1][2] = fma2(hv2.x, w1.x, acc[1][2]); acc[1][2] = fma2(hv2.y, w1.y, acc[1][2]);
                acc[1][3] = fma2(hv3.x, w1.x, acc[1][3]); acc[1][3] = fma2(hv3.y, w1.y, acc[1][3]);
                acc[2][0] = fma2(hv0.x, w2.x, acc[2][0]); acc[2][0] = fma2(hv0.y, w2.y, acc[2][0]);
                acc[2][1] = fma2(hv1.x, w2.x, acc[2][1]); acc[2][1] = fma2(hv1.y, w2.y, acc[2][1]);
                acc[2][2] = fma2(hv2.x, w2.x, acc[2][2]); acc[2][2] = fma2(hv2.y, w2.y, acc[2][2]);
                acc[2][3] = fma2(hv3.x, w2.x, acc[2][3]); acc[2][3] = fma2(hv3.y, w2.y, acc[2][3]);
            }

            #pragma unroll
            for (int i = 0; i < 3; i++)
                #pragma unroll
                for (int j = 0; j < 4; j++)
                    P[(ks * 96 + r0 + i) * 17 + bq * 4 + j] = unpack_sum(acc[i][j]);
        }
        __syncthreads();

        // cell update
        float hv = 0.f;
        if (cellv) {
            bool valid = (t < sent_s[lb]);
            float g4[4];
            #pragma unroll
            for (int g = 0; g < 4; g++) {
                int r = g * 24 + u;
                float sum = P[(0 * 96 + r) * 17 + lb] + P[(1 * 96 + r) * 17 + lb]
                          + P[(2 * 96 + r) * 17 + lb] + P[(3 * 96 + r) * 17 + lb];
                g4[g] = sum + (valid ? xp[g] : bias_s[r]);
            }
            float ig = sig_fast(g4[0]), fg = sig_fast(g4[1]);
            float cg = tanh_fast(g4[2]), og = sig_fast(g4[3]);
            creg = fg * creg + ig * cg;
            hv = og * tanh_fast(creg);
            g_h[((dir * 2 + (p ^ 1)) * BN + gb) * HN + gj] = hv;
        }
        __syncthreads();

        // group barrier (16 arrivals); hide g_lstm store under the wait
        if (tid == 0) {
            __threadfence();
            unsigned old = atom_add_acqrel(&g_bcnt[gid], 1u);
            if (((old + 1) & 15u) == 0u)
                st_release_u32(&g_bgen[gid], my_gen + 1);
        }
        if (cellv)
            g_lstm[((size_t)gb * SN + t) * (2 * HN) + dir * HN + gj] = hv;
        if (tid == 0) {
            while (ld_acquire(&g_bgen[gid]) == my_gen) { }
            my_gen++;
        }
        __syncthreads();
    }
}

// ---------------- K4: output linear (Wlin cached in smem, 16 rows/block) ----------
__global__ void __launch_bounds__(256) out_kernel(
    const float* __restrict__ Wlin, const float* __restrict__ blin,
    float* __restrict__ out)
{
    extern __shared__ float Wl[];   // 22*768 floats
    int tid = threadIdx.x;
    int lane = tid & 31, w = tid >> 5;
    for (int idx = tid; idx < TN * 768; idx += 256) Wl[idx] = Wlin[idx];
    __syncthreads();

    int base = blockIdx.x * 16;
    #pragma unroll
    for (int rr = 0; rr < 2; rr++) {
        int row = base + w * 2 + rr;
        const float* src = g_lstm + (size_t)row * 768;
        float rs[24];
        #pragma unroll
        for (int i = 0; i < 24; i++) rs[i] = src[lane + 32 * i];
        for (int o = 0; o < TN; o++) {
            const float* wr = &Wl[o * 768];
            float s = 0.f;
            #pragma unroll
            for (int i = 0; i < 24; i++) s += rs[i] * wr[lane + 32 * i];
            #pragma unroll
            for (int off = 16; off; off >>= 1) s += __shfl_down_sync(0xffffffffu, s, off);
            if (lane == 0) out[(size_t)row * TN + o] = s + blin[o];
        }
    }
}

// ---------------- launch -----------------------------------------------------------
extern "C" void kernel_launch(void* const* d_in, const int* in_sizes, int n_in,
                              void* d_out, int out_size) {
    const float* hs   = (const float*)d_in[0];
    const float* h0   = (const float*)d_in[1];
    const float* c0   = (const float*)d_in[2];
    const float* Wihf = (const float*)d_in[3];
    const float* Whhf = (const float*)d_in[4];
    const float* bihf = (const float*)d_in[5];
    const float* bhhf = (const float*)d_in[6];
    const float* Wihb = (const float*)d_in[7];
    const float* Whhb = (const float*)d_in[8];
    const float* bihb = (const float*)d_in[9];
    const float* bhhb = (const float*)d_in[10];
    const float* Wlin = (const float*)d_in[11];
    const float* blin = (const float*)d_in[12];
    const void*  sid  = d_in[13];
    const void*  msk  = d_in[14];

    meta_kernel<<<BN, 256>>>(sid, msk);
    gather_kernel<<<dim3(SN, BN), 192>>>(hs, sid);
    proj_kernel<<<dim3(GN / 64, SN / 128, 2 * BN), 256>>>(Wihf, Wihb, bihf, bhhf, bihb, bhhb);

    const int rec_smem = (96 * 388 + 16 * 388 + 384 * 17 + 96 + 16) * 4;
    cudaFuncSetAttribute(lstm_kernel, cudaFuncAttributeMaxDynamicSharedMemorySize, rec_smem);
    lstm_kernel<<<NBLK_REC, REC_THREADS, rec_smem>>>(Whhf, Whhb, bihf, bhhf, bihb, bhhb, h0, c0);

    const int out_smem = TN * 768 * 4;
    cudaFuncSetAttribute(out_kernel, cudaFuncAttributeMaxDynamicSharedMemorySize, out_smem);
    out_kernel<<<(BN * SN) / 16, 256, out_smem>>>(Wlin, blin, (float*)d_out);
}

// round 8
// speedup vs baseline: 1.4045x; 1.0014x over previous
#include <cuda_runtime.h>
#include <math.h>

#define BN 64
#define SN 512
#define DN 768
#define HN 384
#define GN 1536
#define TN 22

#define NBLK_REC 256
#define REC_THREADS 256

// ---------------- scratch (static device globals; zero-initialized) ---------
__device__ float g_embeds[BN * SN * DN];
__device__ float g_xg[2 * SN * BN * GN];                 // [dir][t][b][4H]
__device__ float g_lstm[BN * SN * 2 * HN];               // [b][t][2H]
__device__ float g_h[2 * 2 * BN * HN];                   // [dir][parity][b][H]
__device__ int   g_n[BN];
__device__ int   g_sent[BN];
__device__ int   g_last[BN];
__device__ unsigned g_bcnt[8];                           // monotonic, per (dir,bgroup)
__device__ unsigned g_bgen[8];

// ---------------- packed fp32x2 / fast math helpers ---------------------------
__device__ __forceinline__ unsigned long long fma2(unsigned long long a,
                                                   unsigned long long b,
                                                   unsigned long long c) {
    unsigned long long d;
    asm("fma.rn.f32x2 %0, %1, %2, %3;" : "=l"(d) : "l"(a), "l"(b), "l"(c));
    return d;
}
__device__ __forceinline__ float unpack_sum(unsigned long long v) {
    float lo, hi;
    asm("mov.b64 {%0, %1}, %2;" : "=f"(lo), "=f"(hi) : "l"(v));
    return lo + hi;
}
__device__ __forceinline__ float tanh_fast(float x) {
    float y;
    asm("tanh.approx.f32 %0, %1;" : "=f"(y) : "f"(x));
    return y;
}
__device__ __forceinline__ float sig_fast(float x) {
    return 0.5f * tanh_fast(0.5f * x) + 0.5f;
}

// ---------------- scoped atomics for the grid barrier --------------------------
__device__ __forceinline__ unsigned atom_add_acqrel(unsigned* p, unsigned v) {
    unsigned old;
    asm volatile("atom.acq_rel.gpu.global.add.u32 %0, [%1], %2;"
                 : "=r"(old) : "l"(p), "r"(v) : "memory");
    return old;
}
__device__ __forceinline__ unsigned ld_acquire(unsigned* p) {
    unsigned v;
    asm volatile("ld.acquire.gpu.global.u32 %0, [%1];" : "=r"(v) : "l"(p) : "memory");
    return v;
}
__device__ __forceinline__ void st_release_u32(unsigned* p, unsigned v) {
    asm volatile("st.release.gpu.global.u32 [%0], %1;" :: "l"(p), "r"(v) : "memory");
}

// ---------------- index helpers -------------------------------------------------
__device__ __forceinline__ long long ld_idx(const void* p, int i, bool is64) {
    return is64 ? ((const long long*)p)[i] : (long long)((const int*)p)[i];
}
__device__ __forceinline__ bool detect_is64(const void* start_ids) {
    return ((const int*)start_ids)[1] == 0;
}

// ---------------- K0: per-batch metadata ----------------------------------------
__global__ void meta_kernel(const void* start_ids, const void* masks) {
    int b = blockIdx.x;
    int tid = threadIdx.x;
    bool is64 = detect_is64(start_ids);
    __shared__ int red[256];
    int cnt = 0, sm = 0;
    for (int t = tid; t < SN; t += 256) {
        long long sv = ld_idx(start_ids, b * SN + t, is64);
        long long mv = ld_idx(masks, b * SN + t, is64);
        cnt += (sv >= 0);
        sm += (int)mv;
    }
    red[tid] = cnt; __syncthreads();
    for (int o = 128; o > 0; o >>= 1) { if (tid < o) red[tid] += red[tid + o]; __syncthreads(); }
    int ntot = red[0]; __syncthreads();
    red[tid] = sm; __syncthreads();
    for (int o = 128; o > 0; o >>= 1) { if (tid < o) red[tid] += red[tid + o]; __syncthreads(); }
    int stot = red[0];
    if (tid == 0) {
        g_n[b] = ntot;
        g_sent[b] = stot;
        long long last = 0;
        if (ntot > 0) last = ld_idx(start_ids, b * SN + ntot - 1, is64);
        g_last[b] = (int)last;
    }
}

// ---------------- K1: align gather -----------------------------------------------
__global__ void gather_kernel(const float* __restrict__ hs, const void* __restrict__ start_ids) {
    int t = blockIdx.x, b = blockIdx.y;
    int sent = g_sent[b];
    if (t >= sent) return;
    bool is64 = detect_is64(start_ids);
    int n = g_n[b];
    long long idx;
    if (t == 0)      idx = 0;
    else if (t < n)  idx = ld_idx(start_ids, b * SN + t, is64) - 1;
    else if (t == n) idx = g_last[b];
    else             idx = 0;
    if (idx < 0) idx = 0;
    if (idx > SN - 1) idx = SN - 1;
    const float4* src = (const float4*)(hs + ((size_t)b * SN + (size_t)idx) * DN);
    float4* dst = (float4*)(g_embeds + ((size_t)b * SN + t) * DN);
    dst[threadIdx.x] = src[threadIdx.x];
}

// ---------------- K2: input projection GEMM (f32x2, cp.async, 2 blocks/SM) -------
__global__ void __launch_bounds__(256, 2) proj_kernel(
    const float* __restrict__ Wf, const float* __restrict__ Wb,
    const float* __restrict__ bihf, const float* __restrict__ bhhf,
    const float* __restrict__ bihb, const float* __restrict__ bhhb)
{
    int b = blockIdx.z & 63;
    int dir = blockIdx.z >> 6;
    int sent = g_sent[b];
    int t0 = blockIdx.y * 128;
    if (t0 >= sent) return;
    int n0 = blockIdx.x * 64;

    const float* W   = dir ? Wb   : Wf;
    const float* bih = dir ? bihb : bihf;
    const float* bhh = dir ? bhhb : bhhf;

    __shared__ float As[2][128][20];
    __shared__ float Bs[2][64][20];

    int tid = threadIdx.x;
    int tx = tid & 15, ty = tid >> 4;
    int bsw = ((tx >> 3) & 1) << 2;

    unsigned long long acc[8][4];
    #pragma unroll
    for (int i = 0; i < 8; i++)
        #pragma unroll
        for (int j = 0; j < 4; j++) acc[i][j] = 0ull;

    #define PROJ_FILL(stg, kt)                                                           \
        do {                                                                             \
            _Pragma("unroll")                                                            \
            for (int f = 0; f < 2; f++) {                                                \
                int lin = tid + f * 256;                                                 \
                int row = lin >> 2;                                                      \
                int c = (lin & 3) * 4;                                                   \
                unsigned sa = (unsigned)__cvta_generic_to_shared(&As[stg][row][c]);      \
                const float* ga = &g_embeds[((size_t)b * SN + t0 + row) * DN + (kt) + c];\
                asm volatile("cp.async.ca.shared.global [%0], [%1], 16;" :: "r"(sa), "l"(ga)); \
            }                                                                            \
            {                                                                            \
                int row = tid >> 2;                                                      \
                int c = (tid & 3) * 4;                                                   \
                int cs = c ^ (((row >> 3) & 1) << 2);                                    \
                unsigned sb = (unsigned)__cvta_generic_to_shared(&Bs[stg][row][cs]);     \
                const float* gb = &W[(size_t)(n0 + row) * DN + (kt) + c];                \
                asm volatile("cp.async.ca.shared.global [%0], [%1], 16;" :: "r"(sb), "l"(gb)); \
            }                                                                            \
            asm volatile("cp.async.commit_group;");                                      \
        } while (0)

    PROJ_FILL(0, 0);
    int st = 0;
    for (int kt = 0; kt < DN; kt += 16) {
        if (kt + 16 < DN) {
            PROJ_FILL(st ^ 1, kt + 16);
            asm volatile("cp.async.wait_group 1;");
        } else {
            asm volatile("cp.async.wait_group 0;");
        }
        __syncthreads();

        #pragma unroll
        for (int k = 0; k < 16; k += 4) {
            unsigned long long b0[4], b1[4];
            #pragma unroll
            for (int j = 0; j < 4; j++) {
                ulonglong2 v = *(const ulonglong2*)&Bs[st][tx + j * 16][k ^ bsw];
                b0[j] = v.x; b1[j] = v.y;
            }
            #pragma unroll
            for (int i = 0; i < 8; i++) {
                ulonglong2 av = *(const ulonglong2*)&As[st][ty + i * 16][k];
                #pragma unroll
                for (int j = 0; j < 4; j++) {
                    acc[i][j] = fma2(av.x, b0[j], acc[i][j]);
                    acc[i][j] = fma2(av.y, b1[j], acc[i][j]);
                }
            }
        }
        __syncthreads();
        st ^= 1;
    }
    #undef PROJ_FILL

    float bsj[4];
    #pragma unroll
    for (int j = 0; j < 4; j++) {
        int n = n0 + tx + j * 16;
        bsj[j] = bih[n] + bhh[n];
    }
    #pragma unroll
    for (int i = 0; i < 8; i++) {
        int t = t0 + ty + i * 16;
        if (t < sent) {
            float* dst = &g_xg[((size_t)(dir * SN + t) * BN + b) * GN + n0 + tx];
            #pragma unroll
            for (int j = 0; j < 4; j++)
                dst[j * 16] = unpack_sum(acc[i][j]) + bsj[j];
        }
    }
}

// ---------------- K3: persistent bidirectional LSTM recurrence --------------------
// 256 blocks, 2/SM. dir = blk>>7; bg = (blk&127)>>5 (16 batches); hsl = blk&31
// (12 hidden units = 48 gate rows; Whh slice 48x384 fp32 in smem = 74.5KB).
// 256 threads = 8 warps: ks = w>>1 (k-split 4, 96k), rg = w&1 (24 rows each).
// Lane: bq = l>>3, rs = l&7. Thread tile: 3 rows x 4 batches (spacing 4: j*4+bq,
// conflict-free h loads) x 96 k, packed f32x2.
// Barrier: 32 blocks per (dir,bg) -> 8 monotonic counters (replay-safe).
__global__ void __launch_bounds__(REC_THREADS, 2) lstm_kernel(
    const float* __restrict__ Whhf, const float* __restrict__ Whhb,
    const float* __restrict__ bihf, const float* __restrict__ bhhf,
    const float* __restrict__ bihb, const float* __restrict__ bhhb,
    const float* __restrict__ h0, const float* __restrict__ c0)
{
    extern __shared__ float sm_[];
    float* ws     = sm_;                          // 48*388 = 18624
    float* hsm    = sm_ + 18624;                  // 16*388 = 6208
    float* P      = sm_ + 18624 + 6208;           // 4*48*17 = 3264
    float* bias_s = P + 3264;                     // 48
    int*   sent_s = (int*)(bias_s + 48);          // 16

    int tid = threadIdx.x;
    int blk = blockIdx.x;
    int dir = blk >> 7;
    int r7  = blk & 127;
    int bg  = r7 >> 5;            // batch group (16 batches)
    int u0  = (r7 & 31) * 12;     // first hidden unit of slice

    const float* Whh = dir ? Whhb : Whhf;
    const float* bih = dir ? bihb : bihf;
    const float* bhh = dir ? bhhb : bhhf;

    // load Whh slice: local row r = gate*12 + u -> global row gate*HN + u0 + u
    for (int idx = tid; idx < 48 * HN; idx += REC_THREADS) {
        int r = idx / HN, k = idx % HN;
        int grow = (r / 12) * HN + u0 + (r % 12);
        ws[r * 388 + k] = Whh[(size_t)grow * HN + k];
    }
    if (tid < 48) {
        int grow = (tid / 12) * HN + u0 + (tid % 12);
        bias_s[tid] = bih[grow] + bhh[grow];
    }
    if (tid < 16) sent_s[tid] = g_sent[bg * 16 + tid];

    // cell ownership: tid < 192: lb = tid/12 (0..15), u = tid%12
    bool cellv = (tid < 192);
    int lb = tid / 12, u = tid % 12;
    int gb = bg * 16 + lb;
    int gj = u0 + u;
    float creg = 0.f;
    if (cellv) {
        g_h[((dir * 2 + 0) * BN + gb) * HN + gj] = h0[((size_t)dir * BN + gb) * HN + gj];
        creg = c0[((size_t)dir * BN + gb) * HN + gj];
    }

    // GEMV coords
    int w    = tid >> 5;
    int ks   = w >> 1;             // 0..3 (warp-uniform)
    int rg   = w & 1;              // 0..1 (warp-uniform)
    int lane = tid & 31;
    int bq   = lane >> 3;          // 0..3 (batches j*4 + bq)
    int rs   = lane & 7;           // 0..7
    int kbase = ks * 96;
    int r0 = rg * 24 + rs * 3;
    const float* wr0 = &ws[(r0 + 0) * 388 + kbase];
    const float* wr1 = &ws[(r0 + 1) * 388 + kbase];
    const float* wr2 = &ws[(r0 + 2) * 388 + kbase];

    int gid = dir * 4 + bg;

    // barrier init: absolute generation (replay-safe, monotonic counters)
    unsigned my_gen = 0;
    if (tid == 0) my_gen = ld_acquire(&g_bgen[gid]);
    __syncthreads();

    // initial barrier: h0 slices published by all 32 blocks of this group
    if (tid == 0) {
        __threadfence();
        unsigned old = atom_add_acqrel(&g_bcnt[gid], 1u);
        if (((old + 1) & 31u) == 0u) {
            st_release_u32(&g_bgen[gid], my_gen + 1);
        } else {
            while (ld_acquire(&g_bgen[gid]) == my_gen) { }
        }
        my_gen++;
    }
    __syncthreads();

    for (int s = 0; s < SN; s++) {
        int p = s & 1;
        int t = dir ? (SN - 1 - s) : s;

        // prefetch xg for the cell (hidden under staging)
        float xp[4];
        if (cellv) {
            const float* xb = &g_xg[((size_t)(dir * SN + t) * BN + gb) * GN + gj];
            #pragma unroll
            for (int g = 0; g < 4; g++) xp[g] = xb[g * HN];
        }

        // stage h slice via cp.async.cg: warp (ks,rg) stages batches rg*8..+8,
        // k-range ks*96..+96 -> 192 16B-chunks / 32 lanes = 6 per lane
        {
            const float* hsrc = g_h + (size_t)((dir * 2 + p) * BN + bg * 16) * HN;
            #pragma unroll
            for (int c = 0; c < 6; c++) {
                int idx = lane + c * 32;           // 0..191
                int sb = rg * 8 + idx / 24;        // batch 0..15
                int kk = (idx % 24) * 4;
                unsigned sd = (unsigned)__cvta_generic_to_shared(&hsm[sb * 388 + kbase + kk]);
                const float* gsrc = hsrc + (size_t)sb * HN + kbase + kk;
                asm volatile("cp.async.cg.shared.global [%0], [%1], 16;" :: "r"(sd), "l"(gsrc));
            }
            asm volatile("cp.async.commit_group;");
            asm volatile("cp.async.wait_group 0;");
        }
        // sync the 64 threads of this ks-group (warps 2ks, 2ks+1 contiguous)
        asm volatile("bar.sync %0, 64;" :: "r"(1 + ks) : "memory");

        // GEMV: 3 rows x 4 batches x 96 k, packed f32x2 (conflict-free loads)
        {
            unsigned long long acc[3][4];
            #pragma unroll
            for (int i = 0; i < 3; i++)
                #pragma unroll
                for (int j = 0; j < 4; j++) acc[i][j] = 0ull;

            #pragma unroll 4
            for (int kk = 0; kk < 96; kk += 4) {
                ulonglong2 hv0 = *(const ulonglong2*)&hsm[(0 * 4 + bq) * 388 + kbase + kk];
                ulonglong2 hv1 = *(const ulonglong2*)&hsm[(1 * 4 + bq) * 388 + kbase + kk];
                ulonglong2 hv2 = *(const ulonglong2*)&hsm[(2 * 4 + bq) * 388 + kbase + kk];
                ulonglong2 hv3 = *(const ulonglong2*)&hsm[(3 * 4 + bq) * 388 + kbase + kk];
                ulonglong2 w0 = *(const ulonglong2*)(wr0 + kk);
                ulonglong2 w1 = *(const ulonglong2*)(wr1 + kk);
                ulonglong2 w2 = *(const ulonglong2*)(wr2 + kk);
                acc[0][0] = fma2(hv0.x, w0.x, acc[0][0]); acc[0][0] = fma2(hv0.y, w0.y, acc[0][0]);
                acc[0][1] = fma2(hv1.x, w0.x, acc[0][1]); acc[0][1] = fma2(hv1.y, w0.y, acc[0][1]);
                acc[0][2] = fma2(hv2.x, w0.x, acc[0][2]); acc[0][2] = fma2(hv2.y, w0.y, acc[0][2]);
                acc[0][3] = fma2(hv3.x, w0.x, acc[0][3]); acc[0][3] = fma2(hv3.y, w0.y, acc[0][3]);
                acc[1][0] = fma2(hv0.x, w1.x, acc[1][0]); acc[1][0] = fma2(hv0.y, w1.y, acc[1][0]);
                acc[1][1] = fma2(hv1.x, w1.x, acc[1][1]); acc[1][1] = fma2(hv1.y, w1.y, acc[1][1]);
                acc[1][2] = fma2(hv2.x, w1.x, acc[1][2]); acc[1][2] = fma2(hv2.y, w1.y, acc[1][2]);
                acc[1][3] = fma2(hv3.x, w1.x, acc[1][3]); acc[1][3] = fma2(hv3.y, w1.y, acc[1][3]);
                acc[2][0] = fma2(hv0.x, w2.x, acc[2][0]); acc[2][0] = fma2(hv0.y, w2.y, acc[2][0]);
                acc[2][1] = fma2(hv1.x, w2.x, acc[2][1]); acc[2][1] = fma2(hv1.y, w2.y, acc[2][1]);
                acc[2][2] = fma2(hv2.x, w2.x, acc[2][2]); acc[2][2] = fma2(hv2.y, w2.y, acc[2][2]);
                acc[2][3] = fma2(hv3.x, w2.x, acc[2][3]); acc[2][3] = fma2(hv3.y, w2.y, acc[2][3]);
            }

            #pragma unroll
            for (int i = 0; i < 3; i++)
                #pragma unroll
                for (int j = 0; j < 4; j++)
                    P[(ks * 48 + r0 + i) * 17 + j * 4 + bq] = unpack_sum(acc[i][j]);
        }
        __syncthreads();

        // cell update
        float hv = 0.f;
        if (cellv) {
            bool valid = (t < sent_s[lb]);
            float g4[4];
            #pragma unroll
            for (int g = 0; g < 4; g++) {
                int r = g * 12 + u;
                float sum = P[(0 * 48 + r) * 17 + lb] + P[(1 * 48 + r) * 17 + lb]
                          + P[(2 * 48 + r) * 17 + lb] + P[(3 * 48 + r) * 17 + lb];
                g4[g] = sum + (valid ? xp[g] : bias_s[r]);
            }
            float ig = sig_fast(g4[0]), fg = sig_fast(g4[1]);
            float cg = tanh_fast(g4[2]), og = sig_fast(g4[3]);
            creg = fg * creg + ig * cg;
            hv = og * tanh_fast(creg);
            g_h[((dir * 2 + (p ^ 1)) * BN + gb) * HN + gj] = hv;
        }
        __syncthreads();

        // group barrier (32 arrivals); hide g_lstm store under the wait
        if (tid == 0) {
            __threadfence();
            unsigned old = atom_add_acqrel(&g_bcnt[gid], 1u);
            if (((old + 1) & 31u) == 0u)
                st_release_u32(&g_bgen[gid], my_gen + 1);
        }
        if (cellv)
            g_lstm[((size_t)gb * SN + t) * (2 * HN) + dir * HN + gj] = hv;
        if (tid == 0) {
            while (ld_acquire(&g_bgen[gid]) == my_gen) { }
            my_gen++;
        }
        __syncthreads();
    }
}

// ---------------- K4: output linear (Wlin cached in smem, 16 rows/block) ----------
__global__ void __launch_bounds__(256) out_kernel(
    const float* __restrict__ Wlin, const float* __restrict__ blin,
    float* __restrict__ out)
{
    extern __shared__ float Wl[];   // 22*768 floats
    int tid = threadIdx.x;
    int lane = tid & 31, w = tid >> 5;
    for (int idx = tid; idx < TN * 768; idx += 256) Wl[idx] = Wlin[idx];
    __syncthreads();

    int base = blockIdx.x * 16;
    #pragma unroll
    for (int rr = 0; rr < 2; rr++) {
        int row = base + w * 2 + rr;
        const float* src = g_lstm + (size_t)row * 768;
        float rs[24];
        #pragma unroll
        for (int i = 0; i < 24; i++) rs[i] = src[lane + 32 * i];
        for (int o = 0; o < TN; o++) {
            const float* wr = &Wl[o * 768];
            float s = 0.f;
            #pragma unroll
            for (int i = 0; i < 24; i++) s += rs[i] * wr[lane + 32 * i];
            #pragma unroll
            for (int off = 16; off; off >>= 1) s += __shfl_down_sync(0xffffffffu, s, off);
            if (lane == 0) out[(size_t)row * TN + o] = s + blin[o];
        }
    }
}

// ---------------- launch -----------------------------------------------------------
extern "C" void kernel_launch(void* const* d_in, const int* in_sizes, int n_in,
                              void* d_out, int out_size) {
    const float* hs   = (const float*)d_in[0];
    const float* h0   = (const float*)d_in[1];
    const float* c0   = (const float*)d_in[2];
    const float* Wihf = (const float*)d_in[3];
    const float* Whhf = (const float*)d_in[4];
    const float* bihf = (const float*)d_in[5];
    const float* bhhf = (const float*)d_in[6];
    const float* Wihb = (const float*)d_in[7];
    const float* Whhb = (const float*)d_in[8];
    const float* bihb = (const float*)d_in[9];
    const float* bhhb = (const float*)d_in[10];
    const float* Wlin = (const float*)d_in[11];
    const float* blin = (const float*)d_in[12];
    const void*  sid  = d_in[13];
    const void*  msk  = d_in[14];

    meta_kernel<<<BN, 256>>>(sid, msk);
    gather_kernel<<<dim3(SN, BN), 192>>>(hs, sid);
    proj_kernel<<<dim3(GN / 64, SN / 128, 2 * BN), 256>>>(Wihf, Wihb, bihf, bhhf, bihb, bhhb);

    const int rec_smem = (48 * 388 + 16 * 388 + 4 * 48 * 17 + 48 + 16) * 4;  // 112,640 B
    cudaFuncSetAttribute(lstm_kernel, cudaFuncAttributeMaxDynamicSharedMemorySize, rec_smem);
    lstm_kernel<<<NBLK_REC, REC_THREADS, rec_smem>>>(Whhf, Whhb, bihf, bhhf, bihb, bhhb, h0, c0);

    const int out_smem = TN * 768 * 4;
    cudaFuncSetAttribute(out_kernel, cudaFuncAttributeMaxDynamicSharedMemorySize, out_smem);
    out_kernel<<<(BN * SN) / 16, 256, out_smem>>>(Wlin, blin, (float*)d_out);
}